// round 15
// baseline (speedup 1.0000x reference)
#include <cuda_runtime.h>
#include <math.h>

// Problem dims
#define B 8
#define S 4096
#define F 128
#define T 16
#define THRESH 0.1f
#define EPS 1e-8f

// Stats tiling (measured-stable shape)
#define NCHUNK 64
#define TY 8
#define RUN 8
#define STATS_BLOCKS (NCHUNK * B)        // 512

// Zero slices: t in {2,5,8,11,14} per b -> 40 slices of 131072 f4 (2MB each).
#define F4_PER_SLICE (S * (F / 4))       // 131072
#define ZBLK_F4 2048                     // per zero-block: 2048 f4 = 32KB
#define ZBLKS_PER_SLICE (F4_PER_SLICE / ZBLK_F4)   // 64
#define NZSLICES (B * 5)                 // 40
#define ZERO_BLOCKS (NZSLICES * ZBLKS_PER_SLICE)   // 2560
#define PRE_BLOCKS (STATS_BLOCKS + ZERO_BLOCKS)    // 3072
#define MAIN_BLOCKS (B * S * (F / 4) / 256)        // 4096

// Scratch: per-(b,f) double accumulators (16KB). k_inv re-zeros for replays.
__device__ double g_sum[B * F];
__device__ double g_sumsq[B * F];
__device__ __align__(16) float g_inv[B * F];

// Fused prologue: blocks [0,512) = diff stats (atomics); blocks [512,3072)
// write the 40 zero t-slices with EVICT-FIRST stores (R14 win: keeps the
// 16MB input L2-resident for k_main's re-read).
__global__ void k_pre(const float4* __restrict__ x, float4* __restrict__ out) {
    int f4 = threadIdx.x;     // 0..31
    int ty = threadIdx.y;     // 0..7
    int tid = ty * 32 + f4;   // 0..255
    int bid = blockIdx.x;

    if (bid >= STATS_BLOCKS) {
        int z = bid - STATS_BLOCKS;              // 0..2559
        int slice = z >> 6;                      // 0..39
        int off = (z & 63) * ZBLK_F4;
        int b = slice / 5;
        int t = 2 + 3 * (slice % 5);             // 2,5,8,11,14
        float4* dst = out + ((size_t)(b * T + t) * F4_PER_SLICE) + off + tid;
        const float4 zero = make_float4(0.f, 0.f, 0.f, 0.f);
        #pragma unroll
        for (int k = 0; k < ZBLK_F4 / 256; k++)
            __stcs(&dst[k * 256], zero);
        return;
    }

    // ---- stats half ----
    int chunk = bid & (NCHUNK - 1);
    int b = bid >> 6;

    int s_start = chunk * (TY * RUN) + ty * RUN;
    const float4* p = x + (size_t)b * S * 32 + (size_t)s_start * 32 + f4;

    float4 prev = (s_start == 0) ? p[0] : p[-32];   // prepend: diff[0] = 0

    float4 s1 = make_float4(0.f, 0.f, 0.f, 0.f);
    float4 s2 = make_float4(0.f, 0.f, 0.f, 0.f);
    #pragma unroll
    for (int j = 0; j < RUN; j++) {
        float4 cur = *p;
        p += 32;
        float dx = cur.x - prev.x, dy = cur.y - prev.y;
        float dz = cur.z - prev.z, dw = cur.w - prev.w;
        s1.x += dx; s1.y += dy; s1.z += dz; s1.w += dw;
        s2.x += dx * dx; s2.y += dy * dy; s2.z += dz * dz; s2.w += dw * dw;
        prev = cur;
    }

    __shared__ float4 sh1[TY][32];
    __shared__ float4 sh2[TY][32];
    sh1[ty][f4] = s1;
    sh2[ty][f4] = s2;
    __syncthreads();

    if (ty == 0) {
        float4 t1 = make_float4(0.f, 0.f, 0.f, 0.f);
        #pragma unroll
        for (int j = 0; j < TY; j++) {
            float4 a = sh1[j][f4];
            t1.x += a.x; t1.y += a.y; t1.z += a.z; t1.w += a.w;
        }
        int idx = b * F + f4 * 4;
        atomicAdd(&g_sum[idx + 0], (double)t1.x);
        atomicAdd(&g_sum[idx + 1], (double)t1.y);
        atomicAdd(&g_sum[idx + 2], (double)t1.z);
        atomicAdd(&g_sum[idx + 3], (double)t1.w);
    } else if (ty == 1) {
        float4 t2 = make_float4(0.f, 0.f, 0.f, 0.f);
        #pragma unroll
        for (int j = 0; j < TY; j++) {
            float4 c = sh2[j][f4];
            t2.x += c.x; t2.y += c.y; t2.z += c.z; t2.w += c.w;
        }
        int idx = b * F + f4 * 4;
        atomicAdd(&g_sumsq[idx + 0], (double)t2.x);
        atomicAdd(&g_sumsq[idx + 1], (double)t2.y);
        atomicAdd(&g_sumsq[idx + 2], (double)t2.z);
        atomicAdd(&g_sumsq[idx + 3], (double)t2.w);
    }
}

// PDL: launched with programmatic serialization; waits for k_pre completion
// only at the grid-dependency sync (block scheduling overlaps k_pre's tail).
__global__ void k_inv() {
    cudaGridDependencySynchronize();
    int i = blockIdx.x * blockDim.x + threadIdx.x;
    if (i < B * F) {
        double m = g_sum[i] / (double)S;
        double var = g_sumsq[i] / (double)S - m * m;
        if (var < 0.0) var = 0.0;
        float sd = (float)sqrt(var);
        g_inv[i] = 1.0f / (sd + EPS);
        g_sum[i] = 0.0;     // re-zero for next call / graph replay
        g_sumsq[i] = 0.0;
    }
}

// Pos/neg expansion with PDL preamble: input loads (dependent on nothing)
// issue BEFORE the grid-dependency sync, overlapping k_pre/k_inv tails;
// only the g_inv read is ordered after the sync.
__global__ void k_main_pn(const float4* __restrict__ x, float4* __restrict__ out) {
    int i = blockIdx.x * 256 + threadIdx.x;  // 0 .. B*S*(F/4)-1
    int f4 = i & 31;
    int s  = (i >> 5) & 4095;
    int b  = i >> 17;

    float4 cur = x[i];
    float4 prv = (s == 0) ? cur : x[i - 32];

    cudaGridDependencySynchronize();

    const float4 inv4 = *reinterpret_cast<const float4*>(&g_inv[b * F + f4 * 4]);

    float ndx = (cur.x - prv.x) * inv4.x;
    float ndy = (cur.y - prv.y) * inv4.y;
    float ndz = (cur.z - prv.z) * inv4.z;
    float ndw = (cur.w - prv.w) * inv4.w;

    float4 pos, neg;
    pos.x = (ndx >=  THRESH) ? 1.f : 0.f;
    pos.y = (ndy >=  THRESH) ? 1.f : 0.f;
    pos.z = (ndz >=  THRESH) ? 1.f : 0.f;
    pos.w = (ndw >=  THRESH) ? 1.f : 0.f;
    neg.x = (-ndx >= THRESH) ? 1.f : 0.f;
    neg.y = (-ndy >= THRESH) ? 1.f : 0.f;
    neg.z = (-ndz >= THRESH) ? 1.f : 0.f;
    neg.w = (-ndw >= THRESH) ? 1.f : 0.f;

    const size_t tstride = (size_t)S * 32;
    size_t obase = ((size_t)b * T * S + s) * 32 + f4;

    #pragma unroll
    for (int t = 0; t < T; t++) {
        int ph = t % 3;
        if (ph == 2) continue;                      // zeros written by k_pre
        out[obase + (size_t)t * tstride] = (ph == 0) ? pos : neg;
    }
}

extern "C" void kernel_launch(void* const* d_in, const int* in_sizes, int n_in,
                              void* d_out, int out_size) {
    const float4* x = (const float4*)d_in[0];
    float4* out = (float4*)d_out;

    dim3 bt(32, TY);
    k_pre<<<PRE_BLOCKS, bt>>>(x, out);

    cudaLaunchAttribute attr[1];
    attr[0].id = cudaLaunchAttributeProgrammaticStreamSerialization;
    attr[0].val.programmaticStreamSerializationAllowed = 1;

    cudaLaunchConfig_t cfg1 = {};
    cfg1.gridDim = dim3(1);
    cfg1.blockDim = dim3(1024);
    cfg1.dynamicSmemBytes = 0;
    cfg1.stream = 0;
    cfg1.attrs = attr;
    cfg1.numAttrs = 1;
    cudaLaunchKernelEx(&cfg1, k_inv);

    cudaLaunchConfig_t cfg2 = {};
    cfg2.gridDim = dim3(MAIN_BLOCKS);
    cfg2.blockDim = dim3(256);
    cfg2.dynamicSmemBytes = 0;
    cfg2.stream = 0;
    cfg2.attrs = attr;
    cfg2.numAttrs = 1;
    cudaLaunchKernelEx(&cfg2, k_main_pn, (const float4*)x, (float4*)out);
}

// round 16
// speedup vs baseline: 1.0178x; 1.0178x over previous
#include <cuda_runtime.h>
#include <math.h>

// Problem dims
#define B 8
#define S 4096
#define F 128
#define T 16
#define THRESH 0.1f
#define EPS 1e-8f

// Stats tiling (measured-stable shape)
#define NCHUNK 64
#define TY 8
#define RUN 8
#define STATS_BLOCKS (NCHUNK * B)        // 512

// Zero slices: t in {2,5,8,11,14} per b -> 40 slices of 131072 f4 (2MB each).
#define F4_PER_SLICE (S * (F / 4))       // 131072
#define ZBLK_F4 2048                     // per zero-block: 2048 f4 = 32KB
#define ZBLKS_PER_SLICE (F4_PER_SLICE / ZBLK_F4)   // 64
#define NZSLICES (B * 5)                 // 40
#define ZERO_BLOCKS (NZSLICES * ZBLKS_PER_SLICE)   // 2560
#define PRE_BLOCKS (STATS_BLOCKS + ZERO_BLOCKS)    // 3072
#define MAIN_BLOCKS (B * S * (F / 4) / 256)        // 4096

// Scratch: per-(b,f) double accumulators (16KB — tiny, so the last-block
// reduce is ~1us; R2-R4 lesson). Last block re-zeros for graph replays.
__device__ double g_sum[B * F];
__device__ double g_sumsq[B * F];
__device__ __align__(16) float g_inv[B * F];
__device__ unsigned g_count;

// Fused prologue: blocks [0,512) = diff stats (atomics) with LAST-BLOCK
// g_inv computation; blocks [512,3072) write the 40 zero t-slices with
// EVICT-FIRST stores (R14 win: keeps the 16MB input L2-resident).
__global__ void k_pre(const float4* __restrict__ x, float4* __restrict__ out) {
    int f4 = threadIdx.x;     // 0..31
    int ty = threadIdx.y;     // 0..7
    int tid = ty * 32 + f4;   // 0..255
    int bid = blockIdx.x;

    if (bid >= STATS_BLOCKS) {
        // ---- zero-writer half (evict-first stores) ----
        int z = bid - STATS_BLOCKS;              // 0..2559
        int slice = z >> 6;                      // 0..39
        int off = (z & 63) * ZBLK_F4;
        int b = slice / 5;
        int t = 2 + 3 * (slice % 5);             // 2,5,8,11,14
        float4* dst = out + ((size_t)(b * T + t) * F4_PER_SLICE) + off + tid;
        const float4 zero = make_float4(0.f, 0.f, 0.f, 0.f);
        #pragma unroll
        for (int k = 0; k < ZBLK_F4 / 256; k++)
            __stcs(&dst[k * 256], zero);
        return;
    }

    // ---- stats half ----
    int chunk = bid & (NCHUNK - 1);
    int b = bid >> 6;

    int s_start = chunk * (TY * RUN) + ty * RUN;
    const float4* p = x + (size_t)b * S * 32 + (size_t)s_start * 32 + f4;

    float4 prev = (s_start == 0) ? p[0] : p[-32];   // prepend: diff[0] = 0

    float4 s1 = make_float4(0.f, 0.f, 0.f, 0.f);
    float4 s2 = make_float4(0.f, 0.f, 0.f, 0.f);
    #pragma unroll
    for (int j = 0; j < RUN; j++) {
        float4 cur = *p;
        p += 32;
        float dx = cur.x - prev.x, dy = cur.y - prev.y;
        float dz = cur.z - prev.z, dw = cur.w - prev.w;
        s1.x += dx; s1.y += dy; s1.z += dz; s1.w += dw;
        s2.x += dx * dx; s2.y += dy * dy; s2.z += dz * dz; s2.w += dw * dw;
        prev = cur;
    }

    __shared__ float4 sh1[TY][32];
    __shared__ float4 sh2[TY][32];
    sh1[ty][f4] = s1;
    sh2[ty][f4] = s2;
    __syncthreads();

    if (ty == 0) {
        float4 t1 = make_float4(0.f, 0.f, 0.f, 0.f);
        #pragma unroll
        for (int j = 0; j < TY; j++) {
            float4 a = sh1[j][f4];
            t1.x += a.x; t1.y += a.y; t1.z += a.z; t1.w += a.w;
        }
        int idx = b * F + f4 * 4;
        atomicAdd(&g_sum[idx + 0], (double)t1.x);
        atomicAdd(&g_sum[idx + 1], (double)t1.y);
        atomicAdd(&g_sum[idx + 2], (double)t1.z);
        atomicAdd(&g_sum[idx + 3], (double)t1.w);
        __threadfence();   // producer fence: REDs visible before ticket
    } else if (ty == 1) {
        float4 t2 = make_float4(0.f, 0.f, 0.f, 0.f);
        #pragma unroll
        for (int j = 0; j < TY; j++) {
            float4 c = sh2[j][f4];
            t2.x += c.x; t2.y += c.y; t2.z += c.z; t2.w += c.w;
        }
        int idx = b * F + f4 * 4;
        atomicAdd(&g_sumsq[idx + 0], (double)t2.x);
        atomicAdd(&g_sumsq[idx + 1], (double)t2.y);
        atomicAdd(&g_sumsq[idx + 2], (double)t2.z);
        atomicAdd(&g_sumsq[idx + 3], (double)t2.w);
        __threadfence();   // producer fence
    }

    // Last stats block computes g_inv (16KB from L2 — cheap) while the
    // zero-writer blocks keep DRAM busy.
    __shared__ bool amLast;
    __syncthreads();
    if (tid == 0)
        amLast = (atomicAdd(&g_count, 1u) == STATS_BLOCKS - 1);
    __syncthreads();
    if (amLast) {
        #pragma unroll
        for (int k = tid; k < B * F; k += 256) {
            double sum = __ldcg(&g_sum[k]);
            double sumsq = __ldcg(&g_sumsq[k]);
            double m = sum / (double)S;
            double var = sumsq / (double)S - m * m;
            if (var < 0.0) var = 0.0;
            float sd = (float)sqrt(var);
            g_inv[k] = 1.0f / (sd + EPS);
            g_sum[k] = 0.0;     // re-zero for next call / graph replay
            g_sumsq[k] = 0.0;
        }
        __syncthreads();
        if (tid == 0) g_count = 0;
    }
}

// Pos/neg expansion: 11 plain stores per thread (zeros written by k_pre).
// Kernel boundary guarantees g_inv visibility.
__global__ void k_main_pn(const float4* __restrict__ x, float4* __restrict__ out) {
    int i = blockIdx.x * 256 + threadIdx.x;  // 0 .. B*S*(F/4)-1
    int f4 = i & 31;
    int s  = (i >> 5) & 4095;
    int b  = i >> 17;

    float4 cur = x[i];
    float4 prv = (s == 0) ? cur : x[i - 32];

    const float4 inv4 = *reinterpret_cast<const float4*>(&g_inv[b * F + f4 * 4]);

    float ndx = (cur.x - prv.x) * inv4.x;
    float ndy = (cur.y - prv.y) * inv4.y;
    float ndz = (cur.z - prv.z) * inv4.z;
    float ndw = (cur.w - prv.w) * inv4.w;

    float4 pos, neg;
    pos.x = (ndx >=  THRESH) ? 1.f : 0.f;
    pos.y = (ndy >=  THRESH) ? 1.f : 0.f;
    pos.z = (ndz >=  THRESH) ? 1.f : 0.f;
    pos.w = (ndw >=  THRESH) ? 1.f : 0.f;
    neg.x = (-ndx >= THRESH) ? 1.f : 0.f;
    neg.y = (-ndy >= THRESH) ? 1.f : 0.f;
    neg.z = (-ndz >= THRESH) ? 1.f : 0.f;
    neg.w = (-ndw >= THRESH) ? 1.f : 0.f;

    const size_t tstride = (size_t)S * 32;
    size_t obase = ((size_t)b * T * S + s) * 32 + f4;

    #pragma unroll
    for (int t = 0; t < T; t++) {
        int ph = t % 3;
        if (ph == 2) continue;                      // zeros written by k_pre
        out[obase + (size_t)t * tstride] = (ph == 0) ? pos : neg;
    }
}

extern "C" void kernel_launch(void* const* d_in, const int* in_sizes, int n_in,
                              void* d_out, int out_size) {
    const float4* x = (const float4*)d_in[0];
    float4* out = (float4*)d_out;

    dim3 bt(32, TY);
    k_pre<<<PRE_BLOCKS, bt>>>(x, out);
    k_main_pn<<<MAIN_BLOCKS, 256>>>(x, out);
}